// round 13
// baseline (speedup 1.0000x reference)
#include <cuda_runtime.h>
#include <cuda_bf16.h>
#include <mma.h>
#include <math.h>
using namespace nvcuda;

// Fixed problem shapes
constexpr int S_ = 128, B_ = 64, I_ = 1024, H_ = 1024, O_ = 1024, T_ = 64;
constexpr int G_ = 4 * H_;          // 4096
constexpr int NB = 148;             // 1 CTA/SM, co-residency guaranteed
constexpr int NT = 512;
constexpr int NTHREADS = NB * NT;

// smem stage layout (bf16 elems): A hi/lo 64x72, W hi/lo 256x72
constexpr int AS_ST = 72, WS_ST = 72;
constexpr int A_HI = 0;
constexpr int A_LO = 64 * AS_ST;
constexpr int W_HI = 2 * 64 * AS_ST;
constexpr int W_LO = W_HI + 256 * WS_ST;
constexpr int STAGE_ELEMS = W_LO + 256 * WS_ST;          // 46080 elems
constexpr int SMEM_BYTES = 2 * STAGE_ELEMS * 2;          // 184320 B

// split-weight storage offsets (elements)
constexpr size_t W_LAYER  = (size_t)G_ * I_;
constexpr size_t OFF_EWIH = 0;
constexpr size_t OFF_EWHH = 2 * W_LAYER;
constexpr size_t OFF_DWIH = 4 * W_LAYER;
constexpr size_t OFF_DWHH = 6 * W_LAYER;
constexpr size_t OFF_LIN  = 8 * W_LAYER;
constexpr size_t NW_TOT   = 8 * W_LAYER + (size_t)O_ * H_;

// ---------------- static device scratch ----------------
__device__ __nv_bfloat16 d_whi[NW_TOT];
__device__ __nv_bfloat16 d_wlo[NW_TOT];
__device__ __nv_bfloat16 d_xs_hi[(size_t)S_ * B_ * I_];
__device__ __nv_bfloat16 d_xs_lo[(size_t)S_ * B_ * I_];
__device__ __nv_bfloat16 d_ys_hi[(size_t)S_ * B_ * H_];
__device__ __nv_bfloat16 d_ys_lo[(size_t)S_ * B_ * H_];
__device__ __nv_bfloat16 d_h_hi[2 * B_ * H_];
__device__ __nv_bfloat16 d_h_lo[2 * B_ * H_];
__device__ __nv_bfloat16 d_x_hi[B_ * I_];
__device__ __nv_bfloat16 d_x_lo[B_ * I_];
__device__ float d_c[2 * B_ * H_];
__device__ float d_part[(size_t)16 * B_ * G_];   // 16 slices x B x G
__device__ volatile unsigned d_flags[NB];
__device__ unsigned g_epoch_base = 0;

// ---------------- atomic-free grid barrier (flag array, monotonic epochs) ----------------
__device__ __forceinline__ void gridbar(unsigned& ep) {
    ep++;
    __syncthreads();
    __threadfence();                              // release: my CTA's writes -> visible
    if (threadIdx.x == 0) d_flags[blockIdx.x] = ep;
    if (threadIdx.x < 32) {
        bool ok;
        do {
            ok = true;
#pragma unroll
            for (int q = 0; q < 5; q++) {
                int i = threadIdx.x + q * 32;
                if (i < NB) ok = ok && (d_flags[i] >= ep);
            }
        } while (!__all_sync(0xffffffffu, ok));
    }
    __syncthreads();
    __threadfence();                              // acquire: see other CTAs' writes
}

// ---------------- cp.async helpers ----------------
__device__ __forceinline__ void cpa16(void* dst, const void* src) {
    unsigned d = (unsigned)__cvta_generic_to_shared(dst);
    asm volatile("cp.async.ca.shared.global [%0], [%1], 16;" :: "r"(d), "l"(src));
}
__device__ __forceinline__ void cpa_commit() {
    asm volatile("cp.async.commit_group;");
}

// stage one 64-K chunk: A(64 rows) + W(256 rows), hi+lo
__device__ __forceinline__ void stage_chunk(
    __nv_bfloat16* sb,
    const __nv_bfloat16* __restrict__ Ahi, const __nv_bfloat16* __restrict__ Alo, int lda,
    const __nv_bfloat16* __restrict__ Whi, const __nv_bfloat16* __restrict__ Wlo, int ldw,
    int kb)
{
    const int tid = threadIdx.x;
    const int ar = tid >> 3, ac = (tid & 7) * 8;
    cpa16(sb + A_HI + ar * AS_ST + ac, Ahi + (size_t)ar * lda + kb + ac);
    cpa16(sb + A_LO + ar * AS_ST + ac, Alo + (size_t)ar * lda + kb + ac);
#pragma unroll
    for (int q = 0; q < 4; q++) {
        int v = tid + q * NT;
        int wr = v >> 3, wc = (v & 7) * 8;
        cpa16(sb + W_HI + wr * WS_ST + wc, Whi + (size_t)wr * ldw + kb + wc);
        cpa16(sb + W_LO + wr * WS_ST + wc, Wlo + (size_t)wr * ldw + kb + wc);
    }
}

// ---------------- tensor tile: C[64 x 256] = A[64,K] @ W[256,K]^T ----------------
// bf16x3 compensated: acc += Ahi*Whi + Ahi*Wlo + Alo*Whi (fp32 accum).
__device__ void mma_tile(
    const __nv_bfloat16* __restrict__ Ahi, const __nv_bfloat16* __restrict__ Alo, int lda,
    const __nv_bfloat16* __restrict__ Whi, const __nv_bfloat16* __restrict__ Wlo, int ldw,
    float* __restrict__ C, int ldc, int K, __nv_bfloat16* sm)
{
    const int w = threadIdx.x >> 5;
    const int m0 = (w >> 3) * 32;       // 0 or 32
    const int n0 = (w & 7) * 32;        // 0..224

    wmma::fragment<wmma::accumulator, 16, 16, 16, float> acc[2][2];
#pragma unroll
    for (int i = 0; i < 2; i++)
#pragma unroll
        for (int j = 0; j < 2; j++) wmma::fill_fragment(acc[i][j], 0.f);

    const int nch = K >> 6;
    stage_chunk(sm, Ahi, Alo, lda, Whi, Wlo, ldw, 0);
    cpa_commit();
    if (nch > 1) {
        stage_chunk(sm + STAGE_ELEMS, Ahi, Alo, lda, Whi, Wlo, ldw, 64);
        cpa_commit();
    }

    for (int i = 0; i < nch; i++) {
        if (i + 1 < nch) asm volatile("cp.async.wait_group 1;");
        else             asm volatile("cp.async.wait_group 0;");
        __syncthreads();

        const __nv_bfloat16* sb = sm + (i & 1) * STAGE_ELEMS;
#pragma unroll
        for (int k16 = 0; k16 < 4; k16++) {
            wmma::fragment<wmma::matrix_a, 16, 16, 16, __nv_bfloat16, wmma::row_major> ahi[2], alo[2];
#pragma unroll
            for (int mi = 0; mi < 2; mi++) {
                wmma::load_matrix_sync(ahi[mi], sb + A_HI + (m0 + mi * 16) * AS_ST + k16 * 16, AS_ST);
                wmma::load_matrix_sync(alo[mi], sb + A_LO + (m0 + mi * 16) * AS_ST + k16 * 16, AS_ST);
            }
#pragma unroll
            for (int nf = 0; nf < 2; nf++) {
                wmma::fragment<wmma::matrix_b, 16, 16, 16, __nv_bfloat16, wmma::col_major> bhi, blo;
                wmma::load_matrix_sync(bhi, sb + W_HI + (n0 + nf * 16) * WS_ST + k16 * 16, WS_ST);
                wmma::load_matrix_sync(blo, sb + W_LO + (n0 + nf * 16) * WS_ST + k16 * 16, WS_ST);
#pragma unroll
                for (int mi = 0; mi < 2; mi++) {
                    wmma::mma_sync(acc[mi][nf], ahi[mi], bhi, acc[mi][nf]);
                    wmma::mma_sync(acc[mi][nf], ahi[mi], blo, acc[mi][nf]);
                    wmma::mma_sync(acc[mi][nf], alo[mi], bhi, acc[mi][nf]);
                }
            }
        }
        __syncthreads();

        if (i + 2 < nch) {
            stage_chunk(sm + (i & 1) * STAGE_ELEMS, Ahi, Alo, lda, Whi, Wlo, ldw, (i + 2) * 64);
            cpa_commit();
        }
    }

#pragma unroll
    for (int mi = 0; mi < 2; mi++)
#pragma unroll
        for (int nf = 0; nf < 2; nf++)
            wmma::store_matrix_sync(C + (size_t)(m0 + mi * 16) * ldc + n0 + nf * 16,
                                    acc[mi][nf], ldc, wmma::mem_row_major);
}

// one-time (per launch) weight split: w = hi(bf16) + lo(bf16)
__device__ void split_w(const float* __restrict__ src, size_t off, size_t n) {
    for (size_t i = blockIdx.x * (size_t)NT + threadIdx.x; i < n; i += NTHREADS) {
        float v = src[i];
        __nv_bfloat16 h = __float2bfloat16(v);
        d_whi[off + i] = h;
        d_wlo[off + i] = __float2bfloat16(v - __bfloat162float(h));
    }
}

__device__ __forceinline__ float sig_(float x) { return 1.f / (1.f + __expf(-x)); }

// pointwise LSTM gates: sum 8 split-K partials; emit h as bf16 hi/lo
__device__ void gates_fn(const float* __restrict__ part, const float* __restrict__ bias,
                         __nv_bfloat16* __restrict__ h_hi, __nv_bfloat16* __restrict__ h_lo,
                         float* __restrict__ c,
                         __nv_bfloat16* __restrict__ ys_hi, __nv_bfloat16* __restrict__ ys_lo)
{
    for (int idx = blockIdx.x * NT + threadIdx.x; idx < B_ * H_; idx += NTHREADS) {
        int b = idx >> 10, n = idx & 1023;
        float gi = bias[n], gf = bias[H_ + n], gg = bias[2 * H_ + n], go = bias[3 * H_ + n];
#pragma unroll
        for (int s = 0; s < 8; s++) {
            const float* p = part + (size_t)s * B_ * G_ + (size_t)b * G_;
            gi += p[n]; gf += p[H_ + n]; gg += p[2 * H_ + n]; go += p[3 * H_ + n];
        }
        float cv = sig_(gf) * c[idx] + sig_(gi) * tanhf(gg);
        float hv = sig_(go) * tanhf(cv);
        c[idx] = cv;
        __nv_bfloat16 hh = __float2bfloat16(hv);
        __nv_bfloat16 hl = __float2bfloat16(hv - __bfloat162float(hh));
        h_hi[idx] = hh; h_lo[idx] = hl;
        if (ys_hi) { ys_hi[idx] = hh; ys_lo[idx] = hl; }
    }
}

// ---------------- whole seq2seq: ONE persistent kernel ----------------
__global__ void __launch_bounds__(NT)
seq2seq_kernel(const float* __restrict__ x_seq,
               const float* __restrict__ enc_wih, const float* __restrict__ enc_whh,
               const float* __restrict__ enc_b,
               const float* __restrict__ dec_wih, const float* __restrict__ dec_whh,
               const float* __restrict__ dec_b,
               const float* __restrict__ lin_w, const float* __restrict__ lin_b,
               float* __restrict__ out)
{
    extern __shared__ __align__(16) __nv_bfloat16 sm[];
    const int bid = blockIdx.x, tid = threadIdx.x;
    unsigned ep = g_epoch_base;     // persists across launches (monotonic flags)

    // one-time splits (recomputed every launch: deterministic)
    split_w(enc_wih, OFF_EWIH, 2 * W_LAYER);
    split_w(enc_whh, OFF_EWHH, 2 * W_LAYER);
    split_w(dec_wih, OFF_DWIH, 2 * W_LAYER);
    split_w(dec_whh, OFF_DWHH, 2 * W_LAYER);
    split_w(lin_w,   OFF_LIN,  (size_t)O_ * H_);
    for (size_t i = bid * (size_t)NT + tid; i < (size_t)S_ * B_ * I_; i += NTHREADS) {
        float v = x_seq[i];
        __nv_bfloat16 h = __float2bfloat16(v);
        d_xs_hi[i] = h;
        d_xs_lo[i] = __float2bfloat16(v - __bfloat162float(h));
    }
    for (int i = bid * NT + tid; i < 2 * B_ * H_; i += NTHREADS) {
        d_h_hi[i] = __float2bfloat16(0.f); d_h_lo[i] = __float2bfloat16(0.f);
        d_c[i] = 0.f;
    }
    for (int i = bid * NT + tid; i < B_ * I_; i += NTHREADS) {
        float v = x_seq[(size_t)(S_ - 1) * B_ * I_ + i];
        __nv_bfloat16 h = __float2bfloat16(v);
        d_x_hi[i] = h;
        d_x_lo[i] = __float2bfloat16(v - __bfloat162float(h));
    }
    gridbar(ep);

    // ===== encoder: 2-layer WAVEFRONT =====
    // wave w: layer0 step w (if w<S) and layer1 step w-1 (if w>=1), same GEMM phase.
    // Each cell: virtual K=2048 (input || h), 16 n-tiles x 8 k-slices (K=256).
    for (int w = 0; w <= S_; w++) {
        const bool c0 = (w < S_), c1 = (w >= 1);
        const int n0 = c0 ? 128 : 0;
        const int tot = n0 + (c1 ? 128 : 0);

        for (int u = bid; u < tot; u += NB) {
            int cell, uu;
            if (u < n0) { cell = 0; uu = u; } else { cell = 1; uu = u - n0; }
            int tn = uu >> 3, ks = uu & 7;
            const __nv_bfloat16 *Ah, *Al;
            size_t woff;
            if (cell == 0) {
                if (ks < 4) {
                    Ah = d_xs_hi + (size_t)w * B_ * I_ + ks * 256;
                    Al = d_xs_lo + (size_t)w * B_ * I_ + ks * 256;
                    woff = OFF_EWIH + (size_t)tn * 256 * I_ + ks * 256;
                } else {
                    Ah = d_h_hi + (ks - 4) * 256;
                    Al = d_h_lo + (ks - 4) * 256;
                    woff = OFF_EWHH + (size_t)tn * 256 * H_ + (ks - 4) * 256;
                }
            } else {
                if (ks < 4) {
                    Ah = d_ys_hi + (size_t)(w - 1) * B_ * H_ + ks * 256;
                    Al = d_ys_lo + (size_t)(w - 1) * B_ * H_ + ks * 256;
                    woff = OFF_EWIH + W_LAYER + (size_t)tn * 256 * I_ + ks * 256;
                } else {
                    Ah = d_h_hi + B_ * H_ + (ks - 4) * 256;
                    Al = d_h_lo + B_ * H_ + (ks - 4) * 256;
                    woff = OFF_EWHH + W_LAYER + (size_t)tn * 256 * H_ + (ks - 4) * 256;
                }
            }
            mma_tile(Ah, Al, 1024, d_whi + woff, d_wlo + woff, 1024,
                     d_part + (size_t)(cell * 8 + ks) * B_ * G_ + tn * 256, G_, 256, sm);
        }
        gridbar(ep);

        if (c0) gates_fn(d_part, enc_b, d_h_hi, d_h_lo, d_c,
                         d_ys_hi + (size_t)w * B_ * H_, d_ys_lo + (size_t)w * B_ * H_);
        if (c1) gates_fn(d_part + (size_t)8 * B_ * G_, enc_b + G_,
                         d_h_hi + B_ * H_, d_h_lo + B_ * H_, d_c + B_ * H_,
                         nullptr, nullptr);
        gridbar(ep);
    }

    // ===== autoregressive decoder =====
    __nv_bfloat16* h0_hi = d_h_hi;            __nv_bfloat16* h0_lo = d_h_lo;
    __nv_bfloat16* h1_hi = d_h_hi + B_ * H_;  __nv_bfloat16* h1_lo = d_h_lo + B_ * H_;
    float* c0p = d_c;
    float* c1p = d_c + B_ * H_;

    for (int t = 0; t < T_; t++) {
#pragma unroll 1
        for (int l = 0; l < 2; l++) {
            const __nv_bfloat16* xin_hi = (l == 0) ? d_x_hi : h0_hi;
            const __nv_bfloat16* xin_lo = (l == 0) ? d_x_lo : h0_lo;
            __nv_bfloat16* hl_hi = (l == 0) ? h0_hi : h1_hi;
            __nv_bfloat16* hl_lo = (l == 0) ? h0_lo : h1_lo;
            float* cl = (l == 0) ? c0p : c1p;
            const size_t wih_off = OFF_DWIH + (size_t)l * W_LAYER;
            const size_t whh_off = OFF_DWHH + (size_t)l * W_LAYER;
            if (bid < 128) {
                int tn = bid >> 3, ks = bid & 7;
                const __nv_bfloat16* Ah; const __nv_bfloat16* Al;
                size_t woff;
                if (ks < 4) { Ah = xin_hi + ks * 256; Al = xin_lo + ks * 256;
                              woff = wih_off + (size_t)tn * 256 * I_ + ks * 256; }
                else        { Ah = hl_hi + (ks - 4) * 256; Al = hl_lo + (ks - 4) * 256;
                              woff = whh_off + (size_t)tn * 256 * H_ + (ks - 4) * 256; }
                mma_tile(Ah, Al, 1024, d_whi + woff, d_wlo + woff, 1024,
                         d_part + (size_t)ks * B_ * G_ + tn * 256, G_, 256, sm);
            }
            gridbar(ep);
            gates_fn(d_part, dec_b + (size_t)l * G_, hl_hi, hl_lo, cl, nullptr, nullptr);
            gridbar(ep);
        }

        // output linear: 4 n-tiles x 16 k-slices (K=64) = 64 units
        if (bid < 64) {
            int tn = bid >> 4, ks = bid & 15;
            const size_t woff = OFF_LIN + (size_t)tn * 256 * H_ + ks * 64;
            mma_tile(h1_hi + ks * 64, h1_lo + ks * 64, H_,
                     d_whi + woff, d_wlo + woff, H_,
                     d_part + (size_t)ks * B_ * O_ + tn * 256, O_, 64, sm);
        }
        gridbar(ep);
        for (int idx = bid * NT + tid; idx < B_ * O_; idx += NTHREADS) {
            int b = idx >> 10, n = idx & 1023;
            float v = lin_b[n];
#pragma unroll
            for (int s = 0; s < 16; s++)
                v += d_part[(size_t)s * B_ * O_ + (size_t)b * O_ + n];
            out[(size_t)b * T_ * O_ + (size_t)t * O_ + n] = v;
            __nv_bfloat16 hh = __float2bfloat16(v);
            d_x_hi[idx] = hh;
            d_x_lo[idx] = __float2bfloat16(v - __bfloat162float(hh));
        }
        gridbar(ep);
    }

    // persist epoch base for the next launch (flags stay at final values)
    if (bid == 0 && tid == 0) g_epoch_base = ep;
}

// ---------------- driver: single launch => single graph node ----------------
extern "C" void kernel_launch(void* const* d_in, const int* in_sizes, int n_in,
                              void* d_out, int out_size)
{
    cudaFuncSetAttribute(seq2seq_kernel,
                         cudaFuncAttributeMaxDynamicSharedMemorySize, SMEM_BYTES);
    seq2seq_kernel<<<NB, NT, SMEM_BYTES>>>(
        (const float*)d_in[0], (const float*)d_in[1], (const float*)d_in[2],
        (const float*)d_in[3], (const float*)d_in[4], (const float*)d_in[5],
        (const float*)d_in[6], (const float*)d_in[7], (const float*)d_in[8],
        (float*)d_out);
}

// round 14
// speedup vs baseline: 1.0240x; 1.0240x over previous
#include <cuda_runtime.h>
#include <cuda_bf16.h>
#include <mma.h>
#include <math.h>
using namespace nvcuda;

// Fixed problem shapes
constexpr int S_ = 128, B_ = 64, I_ = 1024, H_ = 1024, O_ = 1024, T_ = 64;
constexpr int G_ = 4 * H_;          // 4096
constexpr int NB = 148;             // 1 CTA/SM, co-residency guaranteed
constexpr int NT = 512;
constexpr int NTHREADS = NB * NT;

// smem stage layout (bf16 elems): A hi/lo 64x72, W hi/lo 256x72
constexpr int AS_ST = 72, WS_ST = 72;
constexpr int A_HI = 0;
constexpr int A_LO = 64 * AS_ST;
constexpr int W_HI = 2 * 64 * AS_ST;
constexpr int W_LO = W_HI + 256 * WS_ST;
constexpr int STAGE_ELEMS = W_LO + 256 * WS_ST;          // 46080 elems
constexpr int SMEM_BYTES = 2 * STAGE_ELEMS * 2;          // 184320 B

// split-weight storage offsets (elements)
constexpr size_t W_LAYER  = (size_t)G_ * I_;
constexpr size_t OFF_EWIH = 0;
constexpr size_t OFF_EWHH = 2 * W_LAYER;
constexpr size_t OFF_DWIH = 4 * W_LAYER;
constexpr size_t OFF_DWHH = 6 * W_LAYER;
constexpr size_t OFF_LIN  = 8 * W_LAYER;
constexpr size_t NW_TOT   = 8 * W_LAYER + (size_t)O_ * H_;

// ---------------- static device scratch ----------------
__device__ __nv_bfloat16 d_whi[NW_TOT];
__device__ __nv_bfloat16 d_wlo[NW_TOT];
__device__ __nv_bfloat16 d_xs_hi[(size_t)S_ * B_ * I_];
__device__ __nv_bfloat16 d_xs_lo[(size_t)S_ * B_ * I_];
__device__ __nv_bfloat16 d_ys_hi[(size_t)S_ * B_ * H_];
__device__ __nv_bfloat16 d_ys_lo[(size_t)S_ * B_ * H_];
__device__ __nv_bfloat16 d_h_hi[2 * B_ * H_];
__device__ __nv_bfloat16 d_h_lo[2 * B_ * H_];
__device__ __nv_bfloat16 d_x_hi[B_ * I_];
__device__ __nv_bfloat16 d_x_lo[B_ * I_];
__device__ float d_c[2 * B_ * H_];
__device__ float d_P[(size_t)S_ * B_ * G_];
__device__ float d_part[8 * B_ * G_];     // 8 slices x B x G (>= 16 x B x O)
__device__ volatile unsigned d_flags[NB];
__device__ unsigned g_epoch_base = 0;

// ---------------- atomic-free grid barrier (flag array, monotonic epochs) ----------------
__device__ __forceinline__ void gridbar(unsigned& ep) {
    ep++;
    __syncthreads();
    __threadfence();                              // release: my CTA's writes visible
    if (threadIdx.x == 0) d_flags[blockIdx.x] = ep;
    if (threadIdx.x < 32) {
        bool ok;
        do {
            ok = true;
#pragma unroll
            for (int q = 0; q < 5; q++) {
                int i = threadIdx.x + q * 32;
                if (i < NB) ok = ok && (d_flags[i] >= ep);
            }
        } while (!__all_sync(0xffffffffu, ok));
    }
    __syncthreads();
    __threadfence();                              // acquire: see other CTAs' writes
}

// ---------------- cp.async helpers ----------------
__device__ __forceinline__ void cpa16(void* dst, const void* src) {
    unsigned d = (unsigned)__cvta_generic_to_shared(dst);
    asm volatile("cp.async.ca.shared.global [%0], [%1], 16;" :: "r"(d), "l"(src));
}
__device__ __forceinline__ void cpa_commit() {
    asm volatile("cp.async.commit_group;");
}

// stage one 64-K chunk: A(64 rows) + W(256 rows), hi+lo
__device__ __forceinline__ void stage_chunk(
    __nv_bfloat16* sb,
    const __nv_bfloat16* __restrict__ Ahi, const __nv_bfloat16* __restrict__ Alo, int lda,
    const __nv_bfloat16* __restrict__ Whi, const __nv_bfloat16* __restrict__ Wlo, int ldw,
    int kb)
{
    const int tid = threadIdx.x;
    const int ar = tid >> 3, ac = (tid & 7) * 8;
    cpa16(sb + A_HI + ar * AS_ST + ac, Ahi + (size_t)ar * lda + kb + ac);
    cpa16(sb + A_LO + ar * AS_ST + ac, Alo + (size_t)ar * lda + kb + ac);
#pragma unroll
    for (int q = 0; q < 4; q++) {
        int v = tid + q * NT;
        int wr = v >> 3, wc = (v & 7) * 8;
        cpa16(sb + W_HI + wr * WS_ST + wc, Whi + (size_t)wr * ldw + kb + wc);
        cpa16(sb + W_LO + wr * WS_ST + wc, Wlo + (size_t)wr * ldw + kb + wc);
    }
}

// ---------------- tensor tile: C[64 x 256] = A[64,K] @ W[256,K]^T ----------------
// bf16x3 compensated: acc += Ahi*Whi + Ahi*Wlo + Alo*Whi (fp32 accum).
// Operands pre-split bf16 hi/lo in gmem; cp.async double-buffered staging.
__device__ void mma_tile(
    const __nv_bfloat16* __restrict__ Ahi, const __nv_bfloat16* __restrict__ Alo, int lda,
    const __nv_bfloat16* __restrict__ Whi, const __nv_bfloat16* __restrict__ Wlo, int ldw,
    float* __restrict__ C, int ldc, int K, __nv_bfloat16* sm)
{
    const int w = threadIdx.x >> 5;
    const int m0 = (w >> 3) * 32;       // 0 or 32
    const int n0 = (w & 7) * 32;        // 0..224

    wmma::fragment<wmma::accumulator, 16, 16, 16, float> acc[2][2];
#pragma unroll
    for (int i = 0; i < 2; i++)
#pragma unroll
        for (int j = 0; j < 2; j++) wmma::fill_fragment(acc[i][j], 0.f);

    const int nch = K >> 6;
    stage_chunk(sm, Ahi, Alo, lda, Whi, Wlo, ldw, 0);
    cpa_commit();
    if (nch > 1) {
        stage_chunk(sm + STAGE_ELEMS, Ahi, Alo, lda, Whi, Wlo, ldw, 64);
        cpa_commit();
    }

    for (int i = 0; i < nch; i++) {
        if (i + 1 < nch) asm volatile("cp.async.wait_group 1;");
        else             asm volatile("cp.async.wait_group 0;");
        __syncthreads();

        const __nv_bfloat16* sb = sm + (i & 1) * STAGE_ELEMS;
#pragma unroll
        for (int k16 = 0; k16 < 4; k16++) {
            wmma::fragment<wmma::matrix_a, 16, 16, 16, __nv_bfloat16, wmma::row_major> ahi[2], alo[2];
#pragma unroll
            for (int mi = 0; mi < 2; mi++) {
                wmma::load_matrix_sync(ahi[mi], sb + A_HI + (m0 + mi * 16) * AS_ST + k16 * 16, AS_ST);
                wmma::load_matrix_sync(alo[mi], sb + A_LO + (m0 + mi * 16) * AS_ST + k16 * 16, AS_ST);
            }
#pragma unroll
            for (int nf = 0; nf < 2; nf++) {
                wmma::fragment<wmma::matrix_b, 16, 16, 16, __nv_bfloat16, wmma::col_major> bhi, blo;
                wmma::load_matrix_sync(bhi, sb + W_HI + (n0 + nf * 16) * WS_ST + k16 * 16, WS_ST);
                wmma::load_matrix_sync(blo, sb + W_LO + (n0 + nf * 16) * WS_ST + k16 * 16, WS_ST);
#pragma unroll
                for (int mi = 0; mi < 2; mi++) {
                    wmma::mma_sync(acc[mi][nf], ahi[mi], bhi, acc[mi][nf]);
                    wmma::mma_sync(acc[mi][nf], ahi[mi], blo, acc[mi][nf]);
                    wmma::mma_sync(acc[mi][nf], alo[mi], bhi, acc[mi][nf]);
                }
            }
        }
        __syncthreads();

        if (i + 2 < nch) {
            stage_chunk(sm + (i & 1) * STAGE_ELEMS, Ahi, Alo, lda, Whi, Wlo, ldw, (i + 2) * 64);
            cpa_commit();
        }
    }

#pragma unroll
    for (int mi = 0; mi < 2; mi++)
#pragma unroll
        for (int nf = 0; nf < 2; nf++)
            wmma::store_matrix_sync(C + (size_t)(m0 + mi * 16) * ldc + n0 + nf * 16,
                                    acc[mi][nf], ldc, wmma::mem_row_major);
}

// one-time (per launch) weight split: w = hi(bf16) + lo(bf16)
__device__ void split_w(const float* __restrict__ src, size_t off, size_t n) {
    for (size_t i = blockIdx.x * (size_t)NT + threadIdx.x; i < n; i += NTHREADS) {
        float v = src[i];
        __nv_bfloat16 h = __float2bfloat16(v);
        d_whi[off + i] = h;
        d_wlo[off + i] = __float2bfloat16(v - __bfloat162float(h));
    }
}

__device__ __forceinline__ float sig_(float x) { return 1.f / (1.f + __expf(-x)); }

// pointwise LSTM gates: sum 8 split-K partials (+ optional proj); emit h as bf16 hi/lo
__device__ void gates_fn(const float* __restrict__ proj, const float* __restrict__ bias,
                         __nv_bfloat16* __restrict__ h_hi, __nv_bfloat16* __restrict__ h_lo,
                         float* __restrict__ c,
                         __nv_bfloat16* __restrict__ ys_hi, __nv_bfloat16* __restrict__ ys_lo)
{
    for (int idx = blockIdx.x * NT + threadIdx.x; idx < B_ * H_; idx += NTHREADS) {
        int b = idx >> 10, n = idx & 1023;
        float gi = bias[n], gf = bias[H_ + n], gg = bias[2 * H_ + n], go = bias[3 * H_ + n];
        if (proj) {
            const float* p = proj + (size_t)b * G_;
            gi += p[n]; gf += p[H_ + n]; gg += p[2 * H_ + n]; go += p[3 * H_ + n];
        }
#pragma unroll
        for (int s = 0; s < 8; s++) {
            const float* p = d_part + (size_t)s * B_ * G_ + (size_t)b * G_;
            gi += p[n]; gf += p[H_ + n]; gg += p[2 * H_ + n]; go += p[3 * H_ + n];
        }
        float cv = sig_(gf) * c[idx] + sig_(gi) * tanhf(gg);
        float hv = sig_(go) * tanhf(cv);
        c[idx] = cv;
        __nv_bfloat16 hh = __float2bfloat16(hv);
        __nv_bfloat16 hl = __float2bfloat16(hv - __bfloat162float(hh));
        h_hi[idx] = hh; h_lo[idx] = hl;
        if (ys_hi) { ys_hi[idx] = hh; ys_lo[idx] = hl; }
    }
}

// ---------------- whole seq2seq: ONE persistent kernel ----------------
__global__ void __launch_bounds__(NT)
seq2seq_kernel(const float* __restrict__ x_seq,
               const float* __restrict__ enc_wih, const float* __restrict__ enc_whh,
               const float* __restrict__ enc_b,
               const float* __restrict__ dec_wih, const float* __restrict__ dec_whh,
               const float* __restrict__ dec_b,
               const float* __restrict__ lin_w, const float* __restrict__ lin_b,
               float* __restrict__ out)
{
    extern __shared__ __align__(16) __nv_bfloat16 sm[];
    const int bid = blockIdx.x, tid = threadIdx.x;
    unsigned ep = g_epoch_base;     // persists across launches (monotonic flags)

    // one-time splits (recomputed every launch: deterministic)
    split_w(enc_wih, OFF_EWIH, 2 * W_LAYER);
    split_w(enc_whh, OFF_EWHH, 2 * W_LAYER);
    split_w(dec_wih, OFF_DWIH, 2 * W_LAYER);
    split_w(dec_whh, OFF_DWHH, 2 * W_LAYER);
    split_w(lin_w,   OFF_LIN,  (size_t)O_ * H_);
    for (size_t i = bid * (size_t)NT + tid; i < (size_t)S_ * B_ * I_; i += NTHREADS) {
        float v = x_seq[i];
        __nv_bfloat16 h = __float2bfloat16(v);
        d_xs_hi[i] = h;
        d_xs_lo[i] = __float2bfloat16(v - __bfloat162float(h));
    }
    for (int i = bid * NT + tid; i < 2 * B_ * H_; i += NTHREADS) {
        d_h_hi[i] = __float2bfloat16(0.f); d_h_lo[i] = __float2bfloat16(0.f);
        d_c[i] = 0.f;
    }
    for (int i = bid * NT + tid; i < B_ * I_; i += NTHREADS) {
        float v = x_seq[(size_t)(S_ - 1) * B_ * I_ + i];
        __nv_bfloat16 h = __float2bfloat16(v);
        d_x_hi[i] = h;
        d_x_lo[i] = __float2bfloat16(v - __bfloat162float(h));
    }
    gridbar(ep);

    // ===== encoder: 2 stacked layers (one layer at a time: whh stays L2-resident) =====
    for (int l = 0; l < 2; l++) {
        const __nv_bfloat16* in_hi = (l == 0) ? d_xs_hi : d_ys_hi;
        const __nv_bfloat16* in_lo = (l == 0) ? d_xs_lo : d_ys_lo;
        const __nv_bfloat16* wih_hi = d_whi + OFF_EWIH + (size_t)l * W_LAYER;
        const __nv_bfloat16* wih_lo = d_wlo + OFF_EWIH + (size_t)l * W_LAYER;
        const __nv_bfloat16* whh_hi = d_whi + OFF_EWHH + (size_t)l * W_LAYER;
        const __nv_bfloat16* whh_lo = d_wlo + OFF_EWHH + (size_t)l * W_LAYER;
        const float* bias = enc_b + (size_t)l * G_;
        __nv_bfloat16* hl_hi = d_h_hi + l * B_ * H_;
        __nv_bfloat16* hl_lo = d_h_lo + l * B_ * H_;
        float* cl = d_c + l * B_ * H_;

        // batched input projection: 128 m-tiles x 16 n-tiles, K=1024
        for (int u = bid; u < 128 * 16; u += NB) {
            int tm = u >> 4, tn = u & 15;
            mma_tile(in_hi + (size_t)tm * 64 * I_, in_lo + (size_t)tm * 64 * I_, I_,
                     wih_hi + (size_t)tn * 256 * I_, wih_lo + (size_t)tn * 256 * I_, I_,
                     d_P + (size_t)tm * 64 * G_ + tn * 256, G_, I_, sm);
        }
        gridbar(ep);

        // recurrence: 16 n-tiles x 8 k-slices (K=128) = 128 units
        for (int t = 0; t < S_; t++) {
            if (bid < 128) {
                int tn = bid >> 3, ks = bid & 7;
                mma_tile(hl_hi + ks * 128, hl_lo + ks * 128, H_,
                         whh_hi + (size_t)tn * 256 * H_ + ks * 128,
                         whh_lo + (size_t)tn * 256 * H_ + ks * 128, H_,
                         d_part + (size_t)ks * B_ * G_ + tn * 256, G_, 128, sm);
            }
            gridbar(ep);
            gates_fn(d_P + (size_t)t * B_ * G_, bias, hl_hi, hl_lo, cl,
                     (l == 0) ? (d_ys_hi + (size_t)t * B_ * H_) : nullptr,
                     (l == 0) ? (d_ys_lo + (size_t)t * B_ * H_) : nullptr);
            gridbar(ep);
        }
    }

    // ===== autoregressive decoder =====
    __nv_bfloat16* h0_hi = d_h_hi;            __nv_bfloat16* h0_lo = d_h_lo;
    __nv_bfloat16* h1_hi = d_h_hi + B_ * H_;  __nv_bfloat16* h1_lo = d_h_lo + B_ * H_;
    float* c0p = d_c;
    float* c1p = d_c + B_ * H_;

    for (int t = 0; t < T_; t++) {
#pragma unroll 1
        for (int l = 0; l < 2; l++) {
            const __nv_bfloat16* xin_hi = (l == 0) ? d_x_hi : h0_hi;
            const __nv_bfloat16* xin_lo = (l == 0) ? d_x_lo : h0_lo;
            __nv_bfloat16* hl_hi = (l == 0) ? h0_hi : h1_hi;
            __nv_bfloat16* hl_lo = (l == 0) ? h0_lo : h1_lo;
            float* cl = (l == 0) ? c0p : c1p;
            const size_t wih_off = OFF_DWIH + (size_t)l * W_LAYER;
            const size_t whh_off = OFF_DWHH + (size_t)l * W_LAYER;
            // virtual K=2048: slices 0-3 -> x part, 4-7 -> h part (K=256 each)
            if (bid < 128) {
                int tn = bid >> 3, ks = bid & 7;
                const __nv_bfloat16* Ah; const __nv_bfloat16* Al;
                size_t woff;
                if (ks < 4) { Ah = xin_hi + ks * 256; Al = xin_lo + ks * 256;
                              woff = wih_off + (size_t)tn * 256 * I_ + ks * 256; }
                else        { Ah = hl_hi + (ks - 4) * 256; Al = hl_lo + (ks - 4) * 256;
                              woff = whh_off + (size_t)tn * 256 * H_ + (ks - 4) * 256; }
                mma_tile(Ah, Al, 1024, d_whi + woff, d_wlo + woff, 1024,
                         d_part + (size_t)ks * B_ * G_ + tn * 256, G_, 256, sm);
            }
            gridbar(ep);
            gates_fn(nullptr, dec_b + (size_t)l * G_, hl_hi, hl_lo, cl, nullptr, nullptr);
            gridbar(ep);
        }

        // output linear: 4 n-tiles x 16 k-slices (K=64) = 64 units
        if (bid < 64) {
            int tn = bid >> 4, ks = bid & 15;
            const size_t woff = OFF_LIN + (size_t)tn * 256 * H_ + ks * 64;
            mma_tile(h1_hi + ks * 64, h1_lo + ks * 64, H_,
                     d_whi + woff, d_wlo + woff, H_,
                     d_part + (size_t)ks * B_ * O_ + tn * 256, O_, 64, sm);
        }
        gridbar(ep);
        for (int idx = bid * NT + tid; idx < B_ * O_; idx += NTHREADS) {
            int b = idx >> 10, n = idx & 1023;
            float v = lin_b[n];
#pragma unroll
            for (int s = 0; s < 16; s++)
                v += d_part[(size_t)s * B_ * O_ + (size_t)b * O_ + n];
            out[(size_t)b * T_ * O_ + (size_t)t * O_ + n] = v;
            __nv_bfloat16 hh = __float2bfloat16(v);
            d_x_hi[idx] = hh;
            d_x_lo[idx] = __float2bfloat16(v - __bfloat162float(hh));
        }
        gridbar(ep);
    }

    // persist epoch base for the next launch (flags stay at final values)
    if (bid == 0 && tid == 0) g_epoch_base = ep;
}

// ---------------- driver: single launch => single graph node ----------------
extern "C" void kernel_launch(void* const* d_in, const int* in_sizes, int n_in,
                              void* d_out, int out_size)
{
    cudaFuncSetAttribute(seq2seq_kernel,
                         cudaFuncAttributeMaxDynamicSharedMemorySize, SMEM_BYTES);
    seq2seq_kernel<<<NB, NT, SMEM_BYTES>>>(
        (const float*)d_in[0], (const float*)d_in[1], (const float*)d_in[2],
        (const float*)d_in[3], (const float*)d_in[4], (const float*)d_in[5],
        (const float*)d_in[6], (const float*)d_in[7], (const float*)d_in[8],
        (float*)d_out);
}

// round 15
// speedup vs baseline: 1.1989x; 1.1708x over previous
#include <cuda_runtime.h>
#include <cuda_bf16.h>
#include <mma.h>
#include <math.h>
using namespace nvcuda;

// Fixed problem shapes
constexpr int S_ = 128, B_ = 64, I_ = 1024, H_ = 1024, O_ = 1024, T_ = 64;
constexpr int G_ = 4 * H_;          // 4096
constexpr int NB = 148;
constexpr int NT = 512;
constexpr int NTHREADS = NB * NT;

// staging layout (bf16 elems) for mma_tile (proj/decoder): A hi/lo 64x72, W hi/lo 256x72
constexpr int AS_ST = 72, WS_ST = 72;
constexpr int A_HI = 0;
constexpr int A_LO = 64 * AS_ST;
constexpr int W_HI = 2 * 64 * AS_ST;
constexpr int W_LO = W_HI + 256 * WS_ST;
constexpr int STAGE_ELEMS = W_LO + 256 * WS_ST;          // 46080
constexpr int SMEM_BYTES = 2 * STAGE_ELEMS * 2;          // 184320 B

// resident layout for encoder recurrence: W 256x136 hi/lo + A 64x136 hi/lo
constexpr int RS_ST = 136;
constexpr int RW_HI = 0;
constexpr int RW_LO = 256 * RS_ST;
constexpr int RA_HI = 2 * 256 * RS_ST;                   // 69632
constexpr int RA_LO = RA_HI + 64 * RS_ST;                // 78336 (total 87040 el < 92160 cap)

// split-weight storage offsets (elements)
constexpr size_t W_LAYER  = (size_t)G_ * I_;             // 2^22
constexpr size_t OFF_EWIH = 0;
constexpr size_t OFF_EWHH = 2 * W_LAYER;
constexpr size_t OFF_DWIH = 4 * W_LAYER;
constexpr size_t OFF_DWHH = 6 * W_LAYER;
constexpr size_t OFF_LIN  = 8 * W_LAYER;
constexpr size_t NW_TOT   = 8 * W_LAYER + (size_t)O_ * H_;

// ---------------- static device scratch ----------------
__device__ __nv_bfloat16 d_whi[NW_TOT];
__device__ __nv_bfloat16 d_wlo[NW_TOT];
__device__ __nv_bfloat16 d_xs_hi[(size_t)S_ * B_ * I_];
__device__ __nv_bfloat16 d_xs_lo[(size_t)S_ * B_ * I_];
__device__ __nv_bfloat16 d_ys_hi[(size_t)S_ * B_ * H_];
__device__ __nv_bfloat16 d_ys_lo[(size_t)S_ * B_ * H_];
__device__ __nv_bfloat16 d_h_hi[2 * B_ * H_];
__device__ __nv_bfloat16 d_h_lo[2 * B_ * H_];
__device__ __nv_bfloat16 d_x_hi[B_ * I_];
__device__ __nv_bfloat16 d_x_lo[B_ * I_];
__device__ float d_c[2 * B_ * H_];
__device__ float d_P[(size_t)S_ * B_ * G_];
__device__ float d_part[8 * B_ * G_];     // 8 slices x B x G (>= 16 x B x O)
__device__ float d_bpk[4 * G_];           // gate-packed biases: enc l0,l1, dec l0,l1
__device__ unsigned g_bar = 0;
__device__ unsigned g_gen = 0;

// ---------------- grid-wide barrier (R12 atomic version — proven fastest) ----------------
__device__ __forceinline__ void gridbar() {
    __syncthreads();
    if (threadIdx.x == 0) {
        __threadfence();
        unsigned gen = *(volatile unsigned*)&g_gen;
        if (atomicAdd(&g_bar, 1) == NB - 1) {
            g_bar = 0;
            __threadfence();
            atomicAdd(&g_gen, 1);
        } else {
            while (*(volatile unsigned*)&g_gen == gen) { }
        }
        __threadfence();
    }
    __syncthreads();
}

// ---------------- cp.async helpers ----------------
__device__ __forceinline__ void cpa16(void* dst, const void* src) {
    unsigned d = (unsigned)__cvta_generic_to_shared(dst);
    asm volatile("cp.async.ca.shared.global [%0], [%1], 16;" :: "r"(d), "l"(src));
}
__device__ __forceinline__ void cpa_commit() {
    asm volatile("cp.async.commit_group;");
}

// stage one 64-K chunk for mma_tile: A(64 rows) + W(256 rows), hi+lo
__device__ __forceinline__ void stage_chunk(
    __nv_bfloat16* sb,
    const __nv_bfloat16* __restrict__ Ahi, const __nv_bfloat16* __restrict__ Alo, int lda,
    const __nv_bfloat16* __restrict__ Whi, const __nv_bfloat16* __restrict__ Wlo, int ldw,
    int kb)
{
    const int tid = threadIdx.x;
    const int ar = tid >> 3, ac = (tid & 7) * 8;
    cpa16(sb + A_HI + ar * AS_ST + ac, Ahi + (size_t)ar * lda + kb + ac);
    cpa16(sb + A_LO + ar * AS_ST + ac, Alo + (size_t)ar * lda + kb + ac);
#pragma unroll
    for (int q = 0; q < 4; q++) {
        int v = tid + q * NT;
        int wr = v >> 3, wc = (v & 7) * 8;
        cpa16(sb + W_HI + wr * WS_ST + wc, Whi + (size_t)wr * ldw + kb + wc);
        cpa16(sb + W_LO + wr * WS_ST + wc, Wlo + (size_t)wr * ldw + kb + wc);
    }
}

// ---------------- streaming tensor tile: C[64 x 256] = A[64,K] @ W[256,K]^T ----------------
__device__ void mma_tile(
    const __nv_bfloat16* __restrict__ Ahi, const __nv_bfloat16* __restrict__ Alo, int lda,
    const __nv_bfloat16* __restrict__ Whi, const __nv_bfloat16* __restrict__ Wlo, int ldw,
    float* __restrict__ C, int ldc, int K, __nv_bfloat16* sm)
{
    const int w = threadIdx.x >> 5;
    const int m0 = (w >> 3) * 32;
    const int n0 = (w & 7) * 32;

    wmma::fragment<wmma::accumulator, 16, 16, 16, float> acc[2][2];
#pragma unroll
    for (int i = 0; i < 2; i++)
#pragma unroll
        for (int j = 0; j < 2; j++) wmma::fill_fragment(acc[i][j], 0.f);

    const int nch = K >> 6;
    stage_chunk(sm, Ahi, Alo, lda, Whi, Wlo, ldw, 0);
    cpa_commit();
    if (nch > 1) {
        stage_chunk(sm + STAGE_ELEMS, Ahi, Alo, lda, Whi, Wlo, ldw, 64);
        cpa_commit();
    }

    for (int i = 0; i < nch; i++) {
        if (i + 1 < nch) asm volatile("cp.async.wait_group 1;");
        else             asm volatile("cp.async.wait_group 0;");
        __syncthreads();

        const __nv_bfloat16* sb = sm + (i & 1) * STAGE_ELEMS;
#pragma unroll
        for (int k16 = 0; k16 < 4; k16++) {
            wmma::fragment<wmma::matrix_a, 16, 16, 16, __nv_bfloat16, wmma::row_major> ahi[2], alo[2];
#pragma unroll
            for (int mi = 0; mi < 2; mi++) {
                wmma::load_matrix_sync(ahi[mi], sb + A_HI + (m0 + mi * 16) * AS_ST + k16 * 16, AS_ST);
                wmma::load_matrix_sync(alo[mi], sb + A_LO + (m0 + mi * 16) * AS_ST + k16 * 16, AS_ST);
            }
#pragma unroll
            for (int nf = 0; nf < 2; nf++) {
                wmma::fragment<wmma::matrix_b, 16, 16, 16, __nv_bfloat16, wmma::col_major> bhi, blo;
                wmma::load_matrix_sync(bhi, sb + W_HI + (n0 + nf * 16) * WS_ST + k16 * 16, WS_ST);
                wmma::load_matrix_sync(blo, sb + W_LO + (n0 + nf * 16) * WS_ST + k16 * 16, WS_ST);
#pragma unroll
                for (int mi = 0; mi < 2; mi++) {
                    wmma::mma_sync(acc[mi][nf], ahi[mi], bhi, acc[mi][nf]);
                    wmma::mma_sync(acc[mi][nf], ahi[mi], blo, acc[mi][nf]);
                    wmma::mma_sync(acc[mi][nf], alo[mi], bhi, acc[mi][nf]);
                }
            }
        }
        __syncthreads();

        if (i + 2 < nch) {
            stage_chunk(sm + (i & 1) * STAGE_ELEMS, Ahi, Alo, lda, Whi, Wlo, ldw, (i + 2) * 64);
            cpa_commit();
        }
    }

#pragma unroll
    for (int mi = 0; mi < 2; mi++)
#pragma unroll
        for (int nf = 0; nf < 2; nf++)
            wmma::store_matrix_sync(C + (size_t)(m0 + mi * 16) * ldc + n0 + nf * 16,
                                    acc[mi][nf], ldc, wmma::mem_row_major);
}

// ---------------- resident-W recurrence tile (K=128, W pre-staged in smem) ----------------
// Stage the 256x128 hi/lo W slice once per layer.
__device__ void stage_w_res(const __nv_bfloat16* __restrict__ Whi,
                            const __nv_bfloat16* __restrict__ Wlo,
                            __nv_bfloat16* sm)
{
#pragma unroll
    for (int q = 0; q < 8; q++) {
        int v = threadIdx.x + q * NT;        // 0..4095
        int row = v >> 4, c8 = (v & 15) * 8;
        *reinterpret_cast<uint4*>(sm + RW_HI + row * RS_ST + c8) =
            *reinterpret_cast<const uint4*>(Whi + (size_t)row * 1024 + c8);
        *reinterpret_cast<uint4*>(sm + RW_LO + row * RS_ST + c8) =
            *reinterpret_cast<const uint4*>(Wlo + (size_t)row * 1024 + c8);
    }
    __syncthreads();
}

// Per step: stage only A (64x128 hi/lo) and compute against resident W.
__device__ void mma_rec(const __nv_bfloat16* __restrict__ Ahi_g,
                        const __nv_bfloat16* __restrict__ Alo_g,
                        float* __restrict__ C, int ldc, __nv_bfloat16* sm)
{
    const int tid = threadIdx.x;
#pragma unroll
    for (int q = 0; q < 2; q++) {
        int v = tid * 2 + q;                 // 0..1023
        int row = v >> 4, c8 = (v & 15) * 8;
        cpa16(sm + RA_HI + row * RS_ST + c8, Ahi_g + (size_t)row * 1024 + c8);
        cpa16(sm + RA_LO + row * RS_ST + c8, Alo_g + (size_t)row * 1024 + c8);
    }
    cpa_commit();
    asm volatile("cp.async.wait_group 0;");
    __syncthreads();

    const int w = tid >> 5;
    const int m0 = (w >> 3) * 32;
    const int n0 = (w & 7) * 32;

    wmma::fragment<wmma::accumulator, 16, 16, 16, float> acc[2][2];
#pragma unroll
    for (int i = 0; i < 2; i++)
#pragma unroll
        for (int j = 0; j < 2; j++) wmma::fill_fragment(acc[i][j], 0.f);

#pragma unroll
    for (int k16 = 0; k16 < 8; k16++) {
        wmma::fragment<wmma::matrix_a, 16, 16, 16, __nv_bfloat16, wmma::row_major> ahi[2], alo[2];
#pragma unroll
        for (int mi = 0; mi < 2; mi++) {
            wmma::load_matrix_sync(ahi[mi], sm + RA_HI + (m0 + mi * 16) * RS_ST + k16 * 16, RS_ST);
            wmma::load_matrix_sync(alo[mi], sm + RA_LO + (m0 + mi * 16) * RS_ST + k16 * 16, RS_ST);
        }
#pragma unroll
        for (int nf = 0; nf < 2; nf++) {
            wmma::fragment<wmma::matrix_b, 16, 16, 16, __nv_bfloat16, wmma::col_major> bhi, blo;
            wmma::load_matrix_sync(bhi, sm + RW_HI + (n0 + nf * 16) * RS_ST + k16 * 16, RS_ST);
            wmma::load_matrix_sync(blo, sm + RW_LO + (n0 + nf * 16) * RS_ST + k16 * 16, RS_ST);
#pragma unroll
            for (int mi = 0; mi < 2; mi++) {
                wmma::mma_sync(acc[mi][nf], ahi[mi], bhi, acc[mi][nf]);
                wmma::mma_sync(acc[mi][nf], ahi[mi], blo, acc[mi][nf]);
                wmma::mma_sync(acc[mi][nf], alo[mi], bhi, acc[mi][nf]);
            }
        }
    }
#pragma unroll
    for (int mi = 0; mi < 2; mi++)
#pragma unroll
        for (int nf = 0; nf < 2; nf++)
            wmma::store_matrix_sync(C + (size_t)(m0 + mi * 16) * ldc + n0 + nf * 16,
                                    acc[mi][nf], ldc, wmma::mem_row_major);
    __syncthreads();        // protect RA before any re-stage (cheap)
}

// ---------------- weight splitting ----------------
// plain: w = hi + lo
__device__ void split_w(const float* __restrict__ src, size_t off, size_t n) {
    for (size_t i = blockIdx.x * (size_t)NT + threadIdx.x; i < n; i += NTHREADS) {
        float v = src[i];
        __nv_bfloat16 h = __float2bfloat16(v);
        d_whi[off + i] = h;
        d_wlo[off + i] = __float2bfloat16(v - __bfloat162float(h));
    }
}
// gate-packed: packed row p <- orig row ((p&3)*1024 + (p>>2)); K=1024 per layer
__device__ void split_w_packed(const float* __restrict__ src, size_t off, int nlayers) {
    size_t n = (size_t)nlayers << 22;
    for (size_t i = blockIdx.x * (size_t)NT + threadIdx.x; i < n; i += NTHREADS) {
        size_t layer = i >> 22;
        size_t p = (i >> 10) & 4095, k = i & 1023;
        size_t o = (layer << 22) + ((((p & 3) << 10) + (p >> 2)) << 10) + k;
        float v = src[o];
        __nv_bfloat16 h = __float2bfloat16(v);
        d_whi[off + i] = h;
        d_wlo[off + i] = __float2bfloat16(v - __bfloat162float(h));
    }
}

__device__ __forceinline__ float sig_(float x) { return 1.f / (1.f + __expf(-x)); }

// pointwise LSTM gates (gate-packed float4 layout): sum 8 slices (+ optional proj)
__device__ void gates_fn(const float* __restrict__ proj, const float* __restrict__ bias_pk,
                         __nv_bfloat16* __restrict__ h_hi, __nv_bfloat16* __restrict__ h_lo,
                         float* __restrict__ c,
                         __nv_bfloat16* __restrict__ ys_hi, __nv_bfloat16* __restrict__ ys_lo)
{
    for (int idx = blockIdx.x * NT + threadIdx.x; idx < B_ * H_; idx += NTHREADS) {
        int b = idx >> 10, n = idx & 1023;
        float4 g = *reinterpret_cast<const float4*>(bias_pk + 4 * n);
        if (proj) {
            float4 p = *reinterpret_cast<const float4*>(proj + (size_t)b * G_ + 4 * n);
            g.x += p.x; g.y += p.y; g.z += p.z; g.w += p.w;
        }
#pragma unroll
        for (int s = 0; s < 8; s++) {
            float4 p = *reinterpret_cast<const float4*>(
                d_part + (size_t)s * B_ * G_ + (size_t)b * G_ + 4 * n);
            g.x += p.x; g.y += p.y; g.z += p.z; g.w += p.w;
        }
        // packed order: x=i, y=f, z=g, w=o
        float cv = sig_(g.y) * c[idx] + sig_(g.x) * tanhf(g.z);
        float hv = sig_(g.w) * tanhf(cv);
        c[idx] = cv;
        __nv_bfloat16 hh = __float2bfloat16(hv);
        __nv_bfloat16 hl = __float2bfloat16(hv - __bfloat162float(hh));
        h_hi[idx] = hh; h_lo[idx] = hl;
        if (ys_hi) { ys_hi[idx] = hh; ys_lo[idx] = hl; }
    }
}

// ---------------- whole seq2seq: ONE persistent kernel ----------------
__global__ void __launch_bounds__(NT)
seq2seq_kernel(const float* __restrict__ x_seq,
               const float* __restrict__ enc_wih, const float* __restrict__ enc_whh,
               const float* __restrict__ enc_b,
               const float* __restrict__ dec_wih, const float* __restrict__ dec_whh,
               const float* __restrict__ dec_b,
               const float* __restrict__ lin_w, const float* __restrict__ lin_b,
               float* __restrict__ out)
{
    extern __shared__ __align__(16) __nv_bfloat16 sm[];
    const int bid = blockIdx.x, tid = threadIdx.x;

    // one-time splits (recomputed every launch: deterministic)
    split_w_packed(enc_wih, OFF_EWIH, 2);
    split_w_packed(enc_whh, OFF_EWHH, 2);
    split_w_packed(dec_wih, OFF_DWIH, 2);
    split_w_packed(dec_whh, OFF_DWHH, 2);
    split_w(lin_w, OFF_LIN, (size_t)O_ * H_);
    for (int i = bid * NT + tid; i < 4 * G_; i += NTHREADS) {
        int layer = i >> 12, j = i & 4095;
        int n = j >> 2, g = j & 3;
        const float* bsrc = (layer < 2) ? enc_b : dec_b;
        d_bpk[i] = bsrc[(layer & 1) * G_ + g * 1024 + n];
    }
    for (size_t i = bid * (size_t)NT + tid; i < (size_t)S_ * B_ * I_; i += NTHREADS) {
        float v = x_seq[i];
        __nv_bfloat16 h = __float2bfloat16(v);
        d_xs_hi[i] = h;
        d_xs_lo[i] = __float2bfloat16(v - __bfloat162float(h));
    }
    for (int i = bid * NT + tid; i < 2 * B_ * H_; i += NTHREADS) {
        d_h_hi[i] = __float2bfloat16(0.f); d_h_lo[i] = __float2bfloat16(0.f);
        d_c[i] = 0.f;
    }
    for (int i = bid * NT + tid; i < B_ * I_; i += NTHREADS) {
        float v = x_seq[(size_t)(S_ - 1) * B_ * I_ + i];
        __nv_bfloat16 h = __float2bfloat16(v);
        d_x_hi[i] = h;
        d_x_lo[i] = __float2bfloat16(v - __bfloat162float(h));
    }
    gridbar();

    // ===== encoder: 2 stacked layers =====
    for (int l = 0; l < 2; l++) {
        const __nv_bfloat16* in_hi = (l == 0) ? d_xs_hi : d_ys_hi;
        const __nv_bfloat16* in_lo = (l == 0) ? d_xs_lo : d_ys_lo;
        const __nv_bfloat16* wih_hi = d_whi + OFF_EWIH + (size_t)l * W_LAYER;
        const __nv_bfloat16* wih_lo = d_wlo + OFF_EWIH + (size_t)l * W_LAYER;
        const __nv_bfloat16* whh_hi = d_whi + OFF_EWHH + (size_t)l * W_LAYER;
        const __nv_bfloat16* whh_lo = d_wlo + OFF_EWHH + (size_t)l * W_LAYER;
        __nv_bfloat16* hl_hi = d_h_hi + l * B_ * H_;
        __nv_bfloat16* hl_lo = d_h_lo + l * B_ * H_;
        float* cl = d_c + l * B_ * H_;

        // batched input projection: 128 m-tiles x 16 n-tiles, K=1024 (gate-packed N)
        for (int u = bid; u < 128 * 16; u += NB) {
            int tm = u >> 4, tn = u & 15;
            mma_tile(in_hi + (size_t)tm * 64 * I_, in_lo + (size_t)tm * 64 * I_, I_,
                     wih_hi + (size_t)tn * 256 * I_, wih_lo + (size_t)tn * 256 * I_, I_,
                     d_P + (size_t)tm * 64 * G_ + tn * 256, G_, I_, sm);
        }
        gridbar();

        // stage this CTA's resident W slice (invariant across all S_ steps)
        int tn = bid >> 3, ks = bid & 7;
        if (bid < 128)
            stage_w_res(whh_hi + (size_t)tn * 256 * H_ + ks * 128,
                        whh_lo + (size_t)tn * 256 * H_ + ks * 128, sm);

        // recurrence: 16 n-tiles x 8 k-slices (K=128), W resident
        for (int t = 0; t < S_; t++) {
            if (bid < 128)
                mma_rec(hl_hi + ks * 128, hl_lo + ks * 128,
                        d_part + (size_t)ks * B_ * G_ + tn * 256, G_, sm);
            gridbar();
            gates_fn(d_P + (size_t)t * B_ * G_, d_bpk + l * G_, hl_hi, hl_lo, cl,
                     (l == 0) ? (d_ys_hi + (size_t)t * B_ * H_) : nullptr,
                     (l == 0) ? (d_ys_lo + (size_t)t * B_ * H_) : nullptr);
            gridbar();
        }
    }

    // ===== autoregressive decoder =====
    __nv_bfloat16* h0_hi = d_h_hi;            __nv_bfloat16* h0_lo = d_h_lo;
    __nv_bfloat16* h1_hi = d_h_hi + B_ * H_;  __nv_bfloat16* h1_lo = d_h_lo + B_ * H_;
    float* c0p = d_c;
    float* c1p = d_c + B_ * H_;

    for (int t = 0; t < T_; t++) {
#pragma unroll 1
        for (int l = 0; l < 2; l++) {
            const __nv_bfloat16* xin_hi = (l == 0) ? d_x_hi : h0_hi;
            const __nv_bfloat16* xin_lo = (l == 0) ? d_x_lo : h0_lo;
            __nv_bfloat16* hl_hi = (l == 0) ? h0_hi : h1_hi;
            __nv_bfloat16* hl_lo = (l == 0) ? h0_lo : h1_lo;
            float* cl = (l == 0) ? c0p : c1p;
            const size_t wih_off = OFF_DWIH + (size_t)l * W_LAYER;
            const size_t whh_off = OFF_DWHH + (size_t)l * W_LAYER;
            // virtual K=2048: slices 0-3 -> x part, 4-7 -> h part (K=256 each)
            if (bid < 128) {
                int tn = bid >> 3, ks = bid & 7;
                const __nv_bfloat16* Ah; const __nv_bfloat16* Al;
                size_t woff;
                if (ks < 4) { Ah = xin_hi + ks * 256; Al = xin_lo + ks * 256;
                              woff = wih_off + (size_t)tn * 256 * I_ + ks * 256; }
                else        { Ah = hl_hi + (ks - 4) * 256; Al = hl_lo + (ks - 4) * 256;
                              woff = whh_off + (size_t)tn * 256 * H_ + (ks - 4) * 256; }
                mma_tile(Ah, Al, 1024, d_whi + woff, d_wlo + woff, 1024,
                         d_part + (size_t)ks * B_ * G_ + tn * 256, G_, 256, sm);
            }
            gridbar();
            gates_fn(nullptr, d_bpk + (2 + l) * G_, hl_hi, hl_lo, cl, nullptr, nullptr);
            gridbar();
        }

        // output linear: 4 n-tiles x 16 k-slices (K=64) = 64 units (lin_w unpacked)
        if (bid < 64) {
            int tn = bid >> 4, ks = bid & 15;
            const size_t woff = OFF_LIN + (size_t)tn * 256 * H_ + ks * 64;
            mma_tile(h1_hi + ks * 64, h1_lo + ks * 64, H_,
                     d_whi + woff, d_wlo + woff, H_,
                     d_part + (size_t)ks * B_ * O_ + tn * 256, O_, 64, sm);
        }
        gridbar();
        for (int idx = bid * NT + tid; idx < B_ * O_; idx += NTHREADS) {
            int b = idx >> 10, n = idx & 1023;
            float v = lin_b[n];
#pragma unroll
            for (int s = 0; s < 16; s++)
                v += d_part[(size_t)s * B_ * O_ + (size_t)b * O_ + n];
            out[(size_t)b * T_ * O_ + (size_t)t * O_ + n] = v;
            __nv_bfloat16 hh = __float2bfloat16(v);
            d_x_hi[idx] = hh;
            d_x_lo[idx] = __float2bfloat16(v - __bfloat162float(hh));
        }
        gridbar();
    }
}

// ---------------- driver: single launch => single graph node ----------------
extern "C" void kernel_launch(void* const* d_in, const int* in_sizes, int n_in,
                              void* d_out, int out_size)
{
    cudaFuncSetAttribute(seq2seq_kernel,
                         cudaFuncAttributeMaxDynamicSharedMemorySize, SMEM_BYTES);
    seq2seq_kernel<<<NB, NT, SMEM_BYTES>>>(
        (const float*)d_in[0], (const float*)d_in[1], (const float*)d_in[2],
        (const float*)d_in[3], (const float*)d_in[4], (const float*)d_in[5],
        (const float*)d_in[6], (const float*)d_in[7], (const float*)d_in[8],
        (float*)d_out);
}